// round 4
// baseline (speedup 1.0000x reference)
#include <cuda_runtime.h>
#include <math.h>
#include <stddef.h>

// Problem constants (B=1)
#define S_LEN  4096
#define DMODEL 512
#define IN_DIM 512
#define NHEAD  8
#define DKH    64          // head dim

// ---------------- scratch (device globals; no allocations allowed) ----------
__device__ float g_Q[S_LEN * DMODEL];
__device__ float g_K[S_LEN * DMODEL];
__device__ float g_V[S_LEN * DMODEL];
__device__ float g_AO[S_LEN * DMODEL];
__device__ unsigned long long g_MB[S_LEN * (S_LEN / 64)];   // bit-packed mask

// ---------------- helpers ----------------------------------------------------
__device__ __forceinline__ unsigned f2tf32(float x) {
    unsigned u;
    asm("cvt.rna.tf32.f32 %0, %1;" : "=r"(u) : "f"(x));
    return u;
}
__device__ __forceinline__ float f2tf32f(float x) {
    return __uint_as_float(f2tf32(x));
}
__device__ __forceinline__ float ex2f(float x) {
    float y;
    asm("ex2.approx.ftz.f32 %0, %1;" : "=f"(y) : "f"(x));
    return y;
}
__device__ __forceinline__ void cpa16(unsigned dst_smem, const void* src) {
    asm volatile("cp.async.cg.shared.global [%0], [%1], 16;\n"
                 :: "r"(dst_smem), "l"(src));
}
#define CP_COMMIT() asm volatile("cp.async.commit_group;\n" ::: "memory")
#define CP_WAIT0()  asm volatile("cp.async.wait_group 0;\n" ::: "memory")

__device__ __forceinline__ void mma_tf32(float c[4],
    unsigned a0, unsigned a1, unsigned a2, unsigned a3,
    unsigned b0, unsigned b1)
{
    asm volatile(
        "mma.sync.aligned.m16n8k8.row.col.f32.tf32.tf32.f32 "
        "{%0,%1,%2,%3}, {%4,%5,%6,%7}, {%8,%9}, {%0,%1,%2,%3};\n"
        : "+f"(c[0]), "+f"(c[1]), "+f"(c[2]), "+f"(c[3])
        : "r"(a0), "r"(a1), "r"(a2), "r"(a3), "r"(b0), "r"(b1));
}

// ============================================================================
// Mask bit-pack: one warp per output uint64 (64 mask columns).
// ============================================================================
__global__ __launch_bounds__(256) void pack_mask_kernel(
    const int* __restrict__ mask, unsigned long long* __restrict__ packed)
{
    const int wid  = (blockIdx.x * blockDim.x + threadIdx.x) >> 5;
    const int lane = threadIdx.x & 31;
    const int row  = wid >> 6;
    const int word = wid & 63;
    const int* p = mask + (size_t)row * S_LEN + word * 64;
    unsigned lo = __ballot_sync(0xffffffffu, p[lane]      != 0);
    unsigned hi = __ballot_sync(0xffffffffu, p[lane + 32] != 0);
    if (lane == 0)
        packed[wid] = ((unsigned long long)hi << 32) | (unsigned long long)lo;
}

// ============================================================================
// tf32 GEMM, cp.async double-buffered: C[m0:+128, n0:+128] = A*B^T + bias
// 8 warps (4 along M x 2 along N), warp tile 32x64. One sync per k-step.
// ============================================================================
#define TGK 16
#define LA  20
#define ABUF (128 * LA)          // one A (or B) stage, floats

__device__ __forceinline__ void gemm_tf32_body(
    const float* __restrict__ A, const float* __restrict__ B,
    const float* __restrict__ bias, float* __restrict__ C,
    int K, int ldc, int m0, int n0, float* As2, float* Bs2)
{
    const int tid  = threadIdx.x;
    const int w    = tid >> 5, lane = tid & 31;
    const int g    = lane >> 2, tig = lane & 3;
    const int wm   = w & 3, wn = w >> 2;
    const int r    = tid >> 2;                 // 0..63
    const int cg   = (tid & 3) * 4;            // 0,4,8,12

    const unsigned sA = (unsigned)__cvta_generic_to_shared(As2);
    const unsigned sB = (unsigned)__cvta_generic_to_shared(Bs2);

    float c[2][8][4];
#pragma unroll
    for (int mt = 0; mt < 2; mt++)
#pragma unroll
        for (int nt = 0; nt < 8; nt++)
#pragma unroll
            for (int j = 0; j < 4; j++) c[mt][nt][j] = 0.f;

    const int nsteps = K / TGK;

    // issue one k-step's copies into buffer bb
    auto issue = [&](int step, int bb) {
        const int k0 = step * TGK;
        unsigned a_dst = sA + (unsigned)(bb * ABUF + r * LA + cg) * 4u;
        unsigned b_dst = sB + (unsigned)(bb * ABUF + r * LA + cg) * 4u;
        cpa16(a_dst,                       A + (size_t)(m0 + r)      * K + k0 + cg);
        cpa16(a_dst + (unsigned)(64 * LA) * 4u, A + (size_t)(m0 + r + 64) * K + k0 + cg);
        cpa16(b_dst,                       B + (size_t)(n0 + r)      * K + k0 + cg);
        cpa16(b_dst + (unsigned)(64 * LA) * 4u, B + (size_t)(n0 + r + 64) * K + k0 + cg);
    };

    issue(0, 0);
    CP_COMMIT();

    for (int i = 0; i < nsteps; i++) {
        CP_WAIT0();
        __syncthreads();
        if (i + 1 < nsteps) { issue(i + 1, (i + 1) & 1); CP_COMMIT(); }

        const float* As = As2 + (i & 1) * ABUF;
        const float* Bs = Bs2 + (i & 1) * ABUF;

#pragma unroll
        for (int kk = 0; kk < 2; kk++) {
            unsigned af[2][4];
#pragma unroll
            for (int mt = 0; mt < 2; mt++) {
                const int row = wm * 32 + mt * 16;
                af[mt][0] = f2tf32(As[(row + g)     * LA + kk * 8 + tig]);
                af[mt][1] = f2tf32(As[(row + g + 8) * LA + kk * 8 + tig]);
                af[mt][2] = f2tf32(As[(row + g)     * LA + kk * 8 + tig + 4]);
                af[mt][3] = f2tf32(As[(row + g + 8) * LA + kk * 8 + tig + 4]);
            }
#pragma unroll
            for (int nt = 0; nt < 8; nt++) {
                const int brow = wn * 64 + nt * 8 + g;
                unsigned bf0 = f2tf32(Bs[brow * LA + kk * 8 + tig]);
                unsigned bf1 = f2tf32(Bs[brow * LA + kk * 8 + tig + 4]);
                mma_tf32(c[0][nt], af[0][0], af[0][1], af[0][2], af[0][3], bf0, bf1);
                mma_tf32(c[1][nt], af[1][0], af[1][1], af[1][2], af[1][3], bf0, bf1);
            }
        }
    }

#pragma unroll
    for (int nt = 0; nt < 8; nt++) {
        const int col = n0 + wn * 64 + nt * 8 + 2 * tig;
        const float2 bv = *(const float2*)(bias + col);
#pragma unroll
        for (int mt = 0; mt < 2; mt++) {
            const int row = m0 + wm * 32 + mt * 16 + g;
            *(float2*)(C + (size_t)row * ldc + col) =
                make_float2(c[mt][nt][0] + bv.x, c[mt][nt][1] + bv.y);
            *(float2*)(C + (size_t)(row + 8) * ldc + col) =
                make_float2(c[mt][nt][2] + bv.x, c[mt][nt][3] + bv.y);
        }
    }
}

__global__ __launch_bounds__(256, 2) void qkv_gemm_kernel(
    const float* __restrict__ x,
    const float* __restrict__ wq, const float* __restrict__ bq,
    const float* __restrict__ wk, const float* __restrict__ bk,
    const float* __restrict__ wv, const float* __restrict__ bv,
    float* __restrict__ Qo, float* __restrict__ Ko, float* __restrict__ Vo)
{
    __shared__ float sm[4 * ABUF];       // 2 stages x (A+B)
    const int nb  = blockIdx.x;          // 0..11
    const int mat = nb >> 2;             // 0:Q 1:K 2:V
    const int n0  = (nb & 3) * 128;
    const int m0  = blockIdx.y * 128;
    const float* B    = (mat == 0) ? wq : (mat == 1) ? wk : wv;
    const float* bias = (mat == 0) ? bq : (mat == 1) ? bk : bv;
    float* C          = (mat == 0) ? Qo : (mat == 1) ? Ko : Vo;
    gemm_tf32_body(x, B, bias, C, IN_DIM, DMODEL, m0, n0, sm, sm + 2 * ABUF);
}

__global__ __launch_bounds__(256, 2) void dense_gemm_kernel(
    const float* __restrict__ A, const float* __restrict__ B,
    const float* __restrict__ bias, float* __restrict__ C)
{
    __shared__ float sm[4 * ABUF];
    gemm_tf32_body(A, B, bias, C, DMODEL, DMODEL,
                   blockIdx.y * 128, blockIdx.x * 128, sm, sm + 2 * ABUF);
}

// ============================================================================
// Flash attention: tf32 mma, cp.async double-buffered K/V, Q-frags in regs,
// bit-packed mask, exp2-domain softmax. Grid (S/128, 8 heads), 256 threads.
// smem: QP region [128][68] (Q, then reused per-warp for P), K 2x[64][68],
// V 2x[64][72]  -> 26624 floats = 104 KB; 2 CTAs/SM.
// ============================================================================
#define BQ   128
#define BKC  64
#define LQ   68
#define LK   68
#define LV   72
#define KBUF (BKC * LK)
#define VBUF (BKC * LV)

#define ATTN_SMEM_FLOATS (BQ * LQ + 2 * KBUF + 2 * VBUF)
#define ATTN_SMEM_BYTES  (ATTN_SMEM_FLOATS * 4)

#define SCALE2 0.1803368801f   // 0.125 * log2(e)

__global__ __launch_bounds__(256, 2) void attn_tc_kernel(
    const float* __restrict__ Q, const float* __restrict__ K,
    const float* __restrict__ V, const unsigned long long* __restrict__ mbits,
    float* __restrict__ O)
{
    extern __shared__ float sm[];
    float* QPs = sm;                       // [BQ][LQ] : Q, later P (per-warp rows)
    float* Ks  = sm + BQ * LQ;             // 2 x [BKC][LK]
    float* Vs  = Ks + 2 * KBUF;            // 2 x [BKC][LV]

    const unsigned sQP = (unsigned)__cvta_generic_to_shared(QPs);
    const unsigned sK  = (unsigned)__cvta_generic_to_shared(Ks);
    const unsigned sV  = (unsigned)__cvta_generic_to_shared(Vs);

    const int tid  = threadIdx.x;
    const int w    = tid >> 5;
    const int lane = tid & 31;
    const int g    = lane >> 2;
    const int tig  = lane & 3;
    const int h    = blockIdx.y;
    const int qb   = blockIdx.x;
    const int w16  = w * 16;

    const float* Qg = Q + ((size_t)h * S_LEN + (size_t)qb * BQ) * DKH;
    const float* Kg = K + (size_t)h * S_LEN * DKH;
    const float* Vg = V + (size_t)h * S_LEN * DKH;

    // thread's copy slice: 4 rows-of-16B for K and V per chunk
    const int crow = tid >> 4;             // 0..15
    const int ccol = (tid & 15) * 4;       // 0,4,..,60

    auto issue_kv = [&](int kb, int bb) {
#pragma unroll
        for (int p = 0; p < 4; p++) {
            const int row = crow + p * 16;
            const size_t goff = (size_t)(kb * BKC + row) * DKH + ccol;
            cpa16(sK + (unsigned)(bb * KBUF + row * LK + ccol) * 4u, Kg + goff);
            cpa16(sV + (unsigned)(bb * VBUF + row * LV + ccol) * 4u, Vg + goff);
        }
    };

    // ---- prologue: Q tile + chunk 0 in flight together ----
#pragma unroll
    for (int p = 0; p < 8; p++) {
        const int f   = tid + p * 256;
        const int row = f >> 4;
        const int col = (f & 15) * 4;
        cpa16(sQP + (unsigned)(row * LQ + col) * 4u, Qg + (size_t)row * DKH + col);
    }
    issue_kv(0, 0);
    CP_COMMIT();
    CP_WAIT0();
    __syncthreads();

    // hoist Q fragments into registers (RN-converted), frees QPs for P reuse
    unsigned qa[8][4];
#pragma unroll
    for (int kk = 0; kk < 8; kk++) {
        qa[kk][0] = f2tf32(QPs[(w16 + g)     * LQ + kk * 8 + tig]);
        qa[kk][1] = f2tf32(QPs[(w16 + g + 8) * LQ + kk * 8 + tig]);
        qa[kk][2] = f2tf32(QPs[(w16 + g)     * LQ + kk * 8 + tig + 4]);
        qa[kk][3] = f2tf32(QPs[(w16 + g + 8) * LQ + kk * 8 + tig + 4]);
    }

    float m0 = -INFINITY, m1 = -INFINITY, l0 = 0.f, l1 = 0.f;
    float o[8][4];
#pragma unroll
    for (int nt = 0; nt < 8; nt++)
#pragma unroll
        for (int j = 0; j < 4; j++) o[nt][j] = 0.f;

    const int row0 = qb * BQ + w16 + g;
    const int row1 = row0 + 8;
    const unsigned long long* mb0p = mbits + (size_t)row0 * 64;
    const unsigned long long* mb1p = mbits + (size_t)row1 * 64;

    for (int kb = 0; kb < S_LEN / BKC; kb++) {
        CP_WAIT0();
        __syncthreads();

        // mask words first (L2 latency hidden by QK mma below)
        const unsigned long long b0 = mb0p[kb] >> (2 * tig);
        const unsigned long long b1 = mb1p[kb] >> (2 * tig);

        if (kb + 1 < S_LEN / BKC) { issue_kv(kb + 1, (kb + 1) & 1); CP_COMMIT(); }

        const float* Kb = Ks + (kb & 1) * KBUF;
        const float* Vb = Vs + (kb & 1) * VBUF;

        // ---- S = Q * K^T (K truncated tf32) ----
        float s[8][4];
#pragma unroll
        for (int nt = 0; nt < 8; nt++)
#pragma unroll
            for (int j = 0; j < 4; j++) s[nt][j] = 0.f;

#pragma unroll
        for (int kk = 0; kk < 8; kk++) {
#pragma unroll
            for (int nt = 0; nt < 8; nt++) {
                unsigned bb0 = __float_as_uint(Kb[(nt * 8 + g) * LK + kk * 8 + tig]);
                unsigned bb1 = __float_as_uint(Kb[(nt * 8 + g) * LK + kk * 8 + tig + 4]);
                mma_tf32(s[nt], qa[kk][0], qa[kk][1], qa[kk][2], qa[kk][3], bb0, bb1);
            }
        }

        // ---- mask + online softmax in exp2 domain ----
        float mx0 = -INFINITY, mx1 = -INFINITY;
#pragma unroll
        for (int nt = 0; nt < 8; nt++) {
            s[nt][0] = fmaf(s[nt][0], SCALE2, ((b0 >> (nt * 8    )) & 1ull) ? -1e9f : 0.f);
            s[nt][1] = fmaf(s[nt][1], SCALE2, ((b0 >> (nt * 8 + 1)) & 1ull) ? -1e9f : 0.f);
            s[nt][2] = fmaf(s[nt][2], SCALE2, ((b1 >> (nt * 8    )) & 1ull) ? -1e9f : 0.f);
            s[nt][3] = fmaf(s[nt][3], SCALE2, ((b1 >> (nt * 8 + 1)) & 1ull) ? -1e9f : 0.f);
            mx0 = fmaxf(mx0, fmaxf(s[nt][0], s[nt][1]));
            mx1 = fmaxf(mx1, fmaxf(s[nt][2], s[nt][3]));
        }
        mx0 = fmaxf(mx0, __shfl_xor_sync(0xffffffffu, mx0, 1));
        mx0 = fmaxf(mx0, __shfl_xor_sync(0xffffffffu, mx0, 2));
        mx1 = fmaxf(mx1, __shfl_xor_sync(0xffffffffu, mx1, 1));
        mx1 = fmaxf(mx1, __shfl_xor_sync(0xffffffffu, mx1, 2));

        const float mn0 = fmaxf(m0, mx0), mn1 = fmaxf(m1, mx1);
        const float sc0 = ex2f(m0 - mn0), sc1 = ex2f(m1 - mn1);
        m0 = mn0; m1 = mn1;

        float rs0 = 0.f, rs1 = 0.f;
#pragma unroll
        for (int nt = 0; nt < 8; nt++) {
            const float p0 = ex2f(s[nt][0] - mn0);
            const float p1 = ex2f(s[nt][1] - mn0);
            const float p2 = ex2f(s[nt][2] - mn1);
            const float p3 = ex2f(s[nt][3] - mn1);
            rs0 += p0 + p1;
            rs1 += p2 + p3;
            *(float2*)&QPs[(w16 + g)     * LQ + nt * 8 + 2 * tig] =
                make_float2(f2tf32f(p0), f2tf32f(p1));
            *(float2*)&QPs[(w16 + g + 8) * LQ + nt * 8 + 2 * tig] =
                make_float2(f2tf32f(p2), f2tf32f(p3));
            o[nt][0] *= sc0; o[nt][1] *= sc0;
            o[nt][2] *= sc1; o[nt][3] *= sc1;
        }
        rs0 += __shfl_xor_sync(0xffffffffu, rs0, 1);
        rs0 += __shfl_xor_sync(0xffffffffu, rs0, 2);
        rs1 += __shfl_xor_sync(0xffffffffu, rs1, 1);
        rs1 += __shfl_xor_sync(0xffffffffu, rs1, 2);
        l0 = l0 * sc0 + rs0;
        l1 = l1 * sc1 + rs1;

        __syncwarp();     // P stores visible within warp (only this warp reads)

        // ---- O += P * V (V truncated tf32) ----
#pragma unroll
        for (int kc = 0; kc < 8; kc++) {
            unsigned a0 = __float_as_uint(QPs[(w16 + g)     * LQ + kc * 8 + tig]);
            unsigned a1 = __float_as_uint(QPs[(w16 + g + 8) * LQ + kc * 8 + tig]);
            unsigned a2 = __float_as_uint(QPs[(w16 + g)     * LQ + kc * 8 + tig + 4]);
            unsigned a3 = __float_as_uint(QPs[(w16 + g + 8) * LQ + kc * 8 + tig + 4]);
#pragma unroll
            for (int nt = 0; nt < 8; nt++) {
                unsigned bb0 = __float_as_uint(Vb[(kc * 8 + tig)     * LV + nt * 8 + g]);
                unsigned bb1 = __float_as_uint(Vb[(kc * 8 + tig + 4) * LV + nt * 8 + g]);
                mma_tf32(o[nt], a0, a1, a2, a3, bb0, bb1);
            }
        }
    }

    // ---- normalize + write AttnOut[token][h*64 + d] ----
    const float inv0 = 1.0f / l0, inv1 = 1.0f / l1;
    float* O0 = O + (size_t)row0 * DMODEL + h * DKH + 2 * tig;
    float* O1 = O + (size_t)row1 * DMODEL + h * DKH + 2 * tig;
#pragma unroll
    for (int nt = 0; nt < 8; nt++) {
        *(float2*)(O0 + nt * 8) = make_float2(o[nt][0] * inv0, o[nt][1] * inv0);
        *(float2*)(O1 + nt * 8) = make_float2(o[nt][2] * inv1, o[nt][3] * inv1);
    }
}

// ============================================================================
extern "C" void kernel_launch(void* const* d_in, const int* in_sizes, int n_in,
                              void* d_out, int out_size)
{
    const float* x       = (const float*)d_in[0];
    const int*   mask    = (const int*)  d_in[1];
    const float* wq_w    = (const float*)d_in[2];
    const float* wq_b    = (const float*)d_in[3];
    const float* wk_w    = (const float*)d_in[4];
    const float* wk_b    = (const float*)d_in[5];
    const float* wv_w    = (const float*)d_in[6];
    const float* wv_b    = (const float*)d_in[7];
    const float* dense_w = (const float*)d_in[8];
    const float* dense_b = (const float*)d_in[9];
    float* out = (float*)d_out;

    float *Qp, *Kp, *Vp, *AOp;
    unsigned long long* MBp;
    cudaGetSymbolAddress((void**)&Qp,  g_Q);
    cudaGetSymbolAddress((void**)&Kp,  g_K);
    cudaGetSymbolAddress((void**)&Vp,  g_V);
    cudaGetSymbolAddress((void**)&AOp, g_AO);
    cudaGetSymbolAddress((void**)&MBp, g_MB);

    cudaFuncSetAttribute(attn_tc_kernel,
                         cudaFuncAttributeMaxDynamicSharedMemorySize,
                         ATTN_SMEM_BYTES);

    // 0) Bit-pack the mask (S*S int32 -> S x S/64 uint64, 2 MB, L2-resident)
    pack_mask_kernel<<<(S_LEN * 64 * 32) / 256, 256>>>(mask, MBp);

    // 1) Fused QKV projections (tf32 tensor cores, cp.async pipeline)
    qkv_gemm_kernel<<<dim3(12, S_LEN / 128), 256>>>(
        x, wq_w, wq_b, wk_w, wk_b, wv_w, wv_b, Qp, Kp, Vp);

    // 2) Masked flash attention (tf32 tensor cores, cp.async pipeline)
    attn_tc_kernel<<<dim3(S_LEN / BQ, NHEAD), 256, ATTN_SMEM_BYTES>>>(
        Qp, Kp, Vp, MBp, AOp);

    // 3) Dense output projection
    dense_gemm_kernel<<<dim3(DMODEL / 128, S_LEN / 128), 256>>>(
        AOp, dense_w, dense_b, out);
}

// round 5
// speedup vs baseline: 1.5552x; 1.5552x over previous
#include <cuda_runtime.h>
#include <math.h>
#include <stddef.h>

// Problem constants (B=1)
#define S_LEN  4096
#define DMODEL 512
#define IN_DIM 512
#define NHEAD  8
#define DKH    64          // head dim

// ---------------- scratch (device globals; no allocations allowed) ----------
__device__ float g_Q[S_LEN * DMODEL];
__device__ float g_K[S_LEN * DMODEL];
__device__ float g_V[S_LEN * DMODEL];
__device__ float g_AO[S_LEN * DMODEL];
__device__ unsigned long long g_MB[S_LEN * (S_LEN / 64)];   // bit-packed mask

// ---------------- helpers ----------------------------------------------------
__device__ __forceinline__ unsigned f2tf32(float x) {
    unsigned u;
    asm("cvt.rna.tf32.f32 %0, %1;" : "=r"(u) : "f"(x));
    return u;
}
__device__ __forceinline__ float f2tf32f(float x) {
    return __uint_as_float(f2tf32(x));
}
__device__ __forceinline__ float ex2f(float x) {
    float y;
    asm("ex2.approx.ftz.f32 %0, %1;" : "=f"(y) : "f"(x));
    return y;
}
__device__ __forceinline__ void cpa16(unsigned dst_smem, const void* src) {
    asm volatile("cp.async.cg.shared.global [%0], [%1], 16;\n"
                 :: "r"(dst_smem), "l"(src));
}
#define CP_COMMIT() asm volatile("cp.async.commit_group;\n" ::: "memory")
#define CP_WAIT0()  asm volatile("cp.async.wait_group 0;\n" ::: "memory")

__device__ __forceinline__ void ldsm_x4(unsigned addr,
    unsigned& r0, unsigned& r1, unsigned& r2, unsigned& r3)
{
    asm volatile("ldmatrix.sync.aligned.m8n8.x4.shared.b16 {%0,%1,%2,%3}, [%4];\n"
                 : "=r"(r0), "=r"(r1), "=r"(r2), "=r"(r3) : "r"(addr));
}

__device__ __forceinline__ void mma_tf32(float c[4],
    unsigned a0, unsigned a1, unsigned a2, unsigned a3,
    unsigned b0, unsigned b1)
{
    asm volatile(
        "mma.sync.aligned.m16n8k8.row.col.f32.tf32.tf32.f32 "
        "{%0,%1,%2,%3}, {%4,%5,%6,%7}, {%8,%9}, {%0,%1,%2,%3};\n"
        : "+f"(c[0]), "+f"(c[1]), "+f"(c[2]), "+f"(c[3])
        : "r"(a0), "r"(a1), "r"(a2), "r"(a3), "r"(b0), "r"(b1));
}

// ============================================================================
// Mask bit-pack: one warp per output uint64 (64 mask columns).
// ============================================================================
__global__ __launch_bounds__(256) void pack_mask_kernel(
    const int* __restrict__ mask, unsigned long long* __restrict__ packed)
{
    const int wid  = (blockIdx.x * blockDim.x + threadIdx.x) >> 5;
    const int lane = threadIdx.x & 31;
    const int row  = wid >> 6;
    const int word = wid & 63;
    const int* p = mask + (size_t)row * S_LEN + word * 64;
    unsigned lo = __ballot_sync(0xffffffffu, p[lane]      != 0);
    unsigned hi = __ballot_sync(0xffffffffu, p[lane + 32] != 0);
    if (lane == 0)
        packed[wid] = ((unsigned long long)hi << 32) | (unsigned long long)lo;
}

// ============================================================================
// tf32 tensor-core GEMM (R2 known-good version): C = A*B^T + bias, 128x128 tile
// ============================================================================
#define TGK 16
#define LA  20

__device__ __forceinline__ void gemm_tf32_body(
    const float* __restrict__ A, const float* __restrict__ B,
    const float* __restrict__ bias, float* __restrict__ C,
    int K, int ldc, int m0, int n0, float* As, float* Bs)
{
    const int tid  = threadIdx.x;
    const int w    = tid >> 5, lane = tid & 31;
    const int g    = lane >> 2, tig = lane & 3;
    const int wm   = w & 3, wn = w >> 2;       // 4 x 2 warp grid
    const int r    = tid >> 2;                 // 0..63
    const int cg   = (tid & 3) * 4;            // 0,4,8,12

    float c[2][8][4];
#pragma unroll
    for (int mt = 0; mt < 2; mt++)
#pragma unroll
        for (int nt = 0; nt < 8; nt++)
#pragma unroll
            for (int j = 0; j < 4; j++) c[mt][nt][j] = 0.f;

    for (int k0 = 0; k0 < K; k0 += TGK) {
        float4 a0 = *(const float4*)(A + (size_t)(m0 + r)      * K + k0 + cg);
        float4 a1 = *(const float4*)(A + (size_t)(m0 + r + 64) * K + k0 + cg);
        float4 b0 = *(const float4*)(B + (size_t)(n0 + r)      * K + k0 + cg);
        float4 b1 = *(const float4*)(B + (size_t)(n0 + r + 64) * K + k0 + cg);
        float4 ta0 = make_float4(f2tf32f(a0.x), f2tf32f(a0.y), f2tf32f(a0.z), f2tf32f(a0.w));
        float4 ta1 = make_float4(f2tf32f(a1.x), f2tf32f(a1.y), f2tf32f(a1.z), f2tf32f(a1.w));
        float4 tb0 = make_float4(f2tf32f(b0.x), f2tf32f(b0.y), f2tf32f(b0.z), f2tf32f(b0.w));
        float4 tb1 = make_float4(f2tf32f(b1.x), f2tf32f(b1.y), f2tf32f(b1.z), f2tf32f(b1.w));
        __syncthreads();
        *(float4*)(As + (r)      * LA + cg) = ta0;
        *(float4*)(As + (r + 64) * LA + cg) = ta1;
        *(float4*)(Bs + (r)      * LA + cg) = tb0;
        *(float4*)(Bs + (r + 64) * LA + cg) = tb1;
        __syncthreads();

#pragma unroll
        for (int kk = 0; kk < 2; kk++) {
            unsigned af[2][4];
#pragma unroll
            for (int mt = 0; mt < 2; mt++) {
                const int row = wm * 32 + mt * 16;
                af[mt][0] = __float_as_uint(As[(row + g)     * LA + kk * 8 + tig]);
                af[mt][1] = __float_as_uint(As[(row + g + 8) * LA + kk * 8 + tig]);
                af[mt][2] = __float_as_uint(As[(row + g)     * LA + kk * 8 + tig + 4]);
                af[mt][3] = __float_as_uint(As[(row + g + 8) * LA + kk * 8 + tig + 4]);
            }
#pragma unroll
            for (int nt = 0; nt < 8; nt++) {
                const int brow = wn * 64 + nt * 8 + g;
                unsigned bf0 = __float_as_uint(Bs[brow * LA + kk * 8 + tig]);
                unsigned bf1 = __float_as_uint(Bs[brow * LA + kk * 8 + tig + 4]);
                mma_tf32(c[0][nt], af[0][0], af[0][1], af[0][2], af[0][3], bf0, bf1);
                mma_tf32(c[1][nt], af[1][0], af[1][1], af[1][2], af[1][3], bf0, bf1);
            }
        }
    }

#pragma unroll
    for (int nt = 0; nt < 8; nt++) {
        const int col = n0 + wn * 64 + nt * 8 + 2 * tig;
        const float2 bv = *(const float2*)(bias + col);
#pragma unroll
        for (int mt = 0; mt < 2; mt++) {
            const int row = m0 + wm * 32 + mt * 16 + g;
            *(float2*)(C + (size_t)row * ldc + col) =
                make_float2(c[mt][nt][0] + bv.x, c[mt][nt][1] + bv.y);
            *(float2*)(C + (size_t)(row + 8) * ldc + col) =
                make_float2(c[mt][nt][2] + bv.x, c[mt][nt][3] + bv.y);
        }
    }
}

#define GEMM_SMEM_FLOATS (2 * 128 * LA)

__global__ __launch_bounds__(256, 2) void qkv_gemm_kernel(
    const float* __restrict__ x,
    const float* __restrict__ wq, const float* __restrict__ bq,
    const float* __restrict__ wk, const float* __restrict__ bk,
    const float* __restrict__ wv, const float* __restrict__ bv,
    float* __restrict__ Qo, float* __restrict__ Ko, float* __restrict__ Vo)
{
    __shared__ float sm[GEMM_SMEM_FLOATS];
    const int nb  = blockIdx.x;          // 0..11
    const int mat = nb >> 2;             // 0:Q 1:K 2:V
    const int n0  = (nb & 3) * 128;
    const int m0  = blockIdx.y * 128;
    const float* B    = (mat == 0) ? wq : (mat == 1) ? wk : wv;
    const float* bias = (mat == 0) ? bq : (mat == 1) ? bk : bv;
    float* C          = (mat == 0) ? Qo : (mat == 1) ? Ko : Vo;
    gemm_tf32_body(x, B, bias, C, IN_DIM, DMODEL, m0, n0, sm, sm + 128 * LA);
}

__global__ __launch_bounds__(256, 2) void dense_gemm_kernel(
    const float* __restrict__ A, const float* __restrict__ B,
    const float* __restrict__ bias, float* __restrict__ C)
{
    __shared__ float sm[GEMM_SMEM_FLOATS];
    gemm_tf32_body(A, B, bias, C, DMODEL, DMODEL,
                   blockIdx.y * 128, blockIdx.x * 128, sm, sm + 128 * LA);
}

// ============================================================================
// Flash attention v4: 512 threads, BQ=256, 1 CTA/SM (reg headroom, no spills).
// tf32 mma; K/P fragments via ldmatrix.x4; Q frags hoisted to registers;
// cp.async double-buffered K/V (raw fp32 bits -> truncated tf32 operands);
// bit-packed mask; exp2-domain online softmax. P reuses Q smem (per-warp rows).
// ============================================================================
#define BQ   256
#define BKC  64
#define LQ   68
#define LK   68
#define LV   72
#define KBUF (BKC * LK)
#define VBUF (BKC * LV)

#define ATTN_SMEM_FLOATS (BQ * LQ + 2 * KBUF + 2 * VBUF)
#define ATTN_SMEM_BYTES  (ATTN_SMEM_FLOATS * 4)

#define SCALE2 0.1803368801f   // 0.125 * log2(e)

__global__ __launch_bounds__(512, 1) void attn_tc_kernel(
    const float* __restrict__ Q, const float* __restrict__ K,
    const float* __restrict__ V, const unsigned long long* __restrict__ mbits,
    float* __restrict__ O)
{
    extern __shared__ float sm[];
    float* QPs = sm;                       // [BQ][LQ] : Q, then P (per-warp rows)
    float* Ks  = sm + BQ * LQ;             // 2 x [BKC][LK]
    float* Vs  = Ks + 2 * KBUF;            // 2 x [BKC][LV]

    const unsigned sQP = (unsigned)__cvta_generic_to_shared(QPs);
    const unsigned sK  = (unsigned)__cvta_generic_to_shared(Ks);
    const unsigned sV  = (unsigned)__cvta_generic_to_shared(Vs);

    const int tid  = threadIdx.x;
    const int w    = tid >> 5;            // 0..15
    const int lane = tid & 31;
    const int g    = lane >> 2;           // 0..7
    const int tig  = lane & 3;            // 0..3
    const int lrow = lane & 7;            // ldmatrix row within matrix
    const int lm   = lane >> 3;           // ldmatrix matrix select 0..3
    const int h    = blockIdx.y;
    const int qb   = blockIdx.x;
    const int w16  = w * 16;

    const float* Qg = Q + ((size_t)h * S_LEN + (size_t)qb * BQ) * DKH;
    const float* Kg = K + (size_t)h * S_LEN * DKH;
    const float* Vg = V + (size_t)h * S_LEN * DKH;

    // copy slices: K/V chunk 64x64 floats, 1024 float4 / 512 thr = 2 each
    const int crow = tid >> 4;            // 0..31
    const int ccol = (tid & 15) * 4;      // 0,4,..,60

    auto issue_kv = [&](int kb, int bb) {
#pragma unroll
        for (int p = 0; p < 2; p++) {
            const int row = crow + p * 32;
            const size_t goff = (size_t)(kb * BKC + row) * DKH + ccol;
            cpa16(sK + (unsigned)(bb * KBUF + row * LK + ccol) * 4u, Kg + goff);
            cpa16(sV + (unsigned)(bb * VBUF + row * LV + ccol) * 4u, Vg + goff);
        }
    };

    // ---- prologue: Q tile (256x64) + K/V chunk 0, one cp.async group ----
#pragma unroll
    for (int p = 0; p < 8; p++) {
        const int f   = tid + p * 512;
        const int row = f >> 4;
        const int col = (f & 15) * 4;
        cpa16(sQP + (unsigned)(row * LQ + col) * 4u, Qg + (size_t)row * DKH + col);
    }
    issue_kv(0, 0);
    CP_COMMIT();
    CP_WAIT0();
    __syncthreads();

    // hoist Q fragments (RN tf32); frees this warp's QP rows for P reuse
    unsigned qa[8][4];
#pragma unroll
    for (int kk = 0; kk < 8; kk++) {
        qa[kk][0] = f2tf32(QPs[(w16 + g)     * LQ + kk * 8 + tig]);
        qa[kk][1] = f2tf32(QPs[(w16 + g + 8) * LQ + kk * 8 + tig]);
        qa[kk][2] = f2tf32(QPs[(w16 + g)     * LQ + kk * 8 + tig + 4]);
        qa[kk][3] = f2tf32(QPs[(w16 + g + 8) * LQ + kk * 8 + tig + 4]);
    }

    float m0 = -INFINITY, m1 = -INFINITY, l0 = 0.f, l1 = 0.f;
    float o[8][4];
#pragma unroll
    for (int nt = 0; nt < 8; nt++)
#pragma unroll
        for (int j = 0; j < 4; j++) o[nt][j] = 0.f;

    const int row0 = qb * BQ + w16 + g;
    const int row1 = row0 + 8;
    const unsigned long long* mb0p = mbits + (size_t)row0 * 64;
    const unsigned long long* mb1p = mbits + (size_t)row1 * 64;

    // lane-fixed ldmatrix address components
    const unsigned klane = (unsigned)(lrow * LK + lm * 4) * 4u;                    // K frags
    const unsigned plane = sQP +
        (unsigned)(((w16 + (lm & 1) * 8 + lrow) * LQ) + (lm >> 1) * 4) * 4u;       // P frags

    for (int kb = 0; kb < S_LEN / BKC; kb++) {
        CP_WAIT0();
        __syncthreads();

        const unsigned long long b0 = mb0p[kb] >> (2 * tig);
        const unsigned long long b1 = mb1p[kb] >> (2 * tig);

        if (kb + 1 < S_LEN / BKC) { issue_kv(kb + 1, (kb + 1) & 1); CP_COMMIT(); }

        const unsigned kbase = sK + (unsigned)((kb & 1) * KBUF) * 4u + klane;
        const float*   Vb    = Vs + (kb & 1) * VBUF;

        // ---- S = Q * K^T : K B-frags via ldmatrix.x4 (2 k-steps per LDSM) ----
        float s[8][4];
#pragma unroll
        for (int nt = 0; nt < 8; nt++) {
#pragma unroll
            for (int j = 0; j < 4; j++) s[nt][j] = 0.f;
            const unsigned bnt = kbase + (unsigned)(nt * 8 * LK) * 4u;
#pragma unroll
            for (int p = 0; p < 4; p++) {
                unsigned r0, r1, r2, r3;
                ldsm_x4(bnt + (unsigned)(p * 16) * 4u, r0, r1, r2, r3);
                mma_tf32(s[nt], qa[2*p][0], qa[2*p][1], qa[2*p][2], qa[2*p][3], r0, r1);
                mma_tf32(s[nt], qa[2*p+1][0], qa[2*p+1][1], qa[2*p+1][2], qa[2*p+1][3], r2, r3);
            }
        }

        // ---- mask + online softmax (exp2 domain) ----
        float mx0 = -INFINITY, mx1 = -INFINITY;
#pragma unroll
        for (int nt = 0; nt < 8; nt++) {
            s[nt][0] = fmaf(s[nt][0], SCALE2, ((b0 >> (nt * 8    )) & 1ull) ? -1e9f : 0.f);
            s[nt][1] = fmaf(s[nt][1], SCALE2, ((b0 >> (nt * 8 + 1)) & 1ull) ? -1e9f : 0.f);
            s[nt][2] = fmaf(s[nt][2], SCALE2, ((b1 >> (nt * 8    )) & 1ull) ? -1e9f : 0.f);
            s[nt][3] = fmaf(s[nt][3], SCALE2, ((b1 >> (nt * 8 + 1)) & 1ull) ? -1e9f : 0.f);
            mx0 = fmaxf(mx0, fmaxf(s[nt][0], s[nt][1]));
            mx1 = fmaxf(mx1, fmaxf(s[nt][2], s[nt][3]));
        }
        mx0 = fmaxf(mx0, __shfl_xor_sync(0xffffffffu, mx0, 1));
        mx0 = fmaxf(mx0, __shfl_xor_sync(0xffffffffu, mx0, 2));
        mx1 = fmaxf(mx1, __shfl_xor_sync(0xffffffffu, mx1, 1));
        mx1 = fmaxf(mx1, __shfl_xor_sync(0xffffffffu, mx1, 2));

        const float mn0 = fmaxf(m0, mx0), mn1 = fmaxf(m1, mx1);
        const float sc0 = ex2f(m0 - mn0), sc1 = ex2f(m1 - mn1);
        m0 = mn0; m1 = mn1;

        float rs0 = 0.f, rs1 = 0.f;
#pragma unroll
        for (int nt = 0; nt < 8; nt++) {
            const float p0 = ex2f(s[nt][0] - mn0);
            const float p1 = ex2f(s[nt][1] - mn0);
            const float p2 = ex2f(s[nt][2] - mn1);
            const float p3 = ex2f(s[nt][3] - mn1);
            rs0 += p0 + p1;
            rs1 += p2 + p3;
            *(float2*)&QPs[(w16 + g)     * LQ + nt * 8 + 2 * tig] =
                make_float2(f2tf32f(p0), f2tf32f(p1));
            *(float2*)&QPs[(w16 + g + 8) * LQ + nt * 8 + 2 * tig] =
                make_float2(f2tf32f(p2), f2tf32f(p3));
            o[nt][0] *= sc0; o[nt][1] *= sc0;
            o[nt][2] *= sc1; o[nt][3] *= sc1;
        }
        rs0 += __shfl_xor_sync(0xffffffffu, rs0, 1);
        rs0 += __shfl_xor_sync(0xffffffffu, rs0, 2);
        rs1 += __shfl_xor_sync(0xffffffffu, rs1, 1);
        rs1 += __shfl_xor_sync(0xffffffffu, rs1, 2);
        l0 = l0 * sc0 + rs0;
        l1 = l1 * sc1 + rs1;

        __syncwarp();   // P visible within warp (exclusive row ownership)

        // ---- O += P * V : P A-frags via ldmatrix.x4, V scalar (conflict-free) ----
#pragma unroll
        for (int kc = 0; kc < 8; kc++) {
            unsigned a0, a1, a2, a3;
            ldsm_x4(plane + (unsigned)(kc * 8) * 4u, a0, a1, a2, a3);
            const float* vr0 = Vb + (kc * 8 + tig)     * LV + g;
            const float* vr1 = Vb + (kc * 8 + tig + 4) * LV + g;
#pragma unroll
            for (int nt = 0; nt < 8; nt++) {
                unsigned bb0 = __float_as_uint(vr0[nt * 8]);
                unsigned bb1 = __float_as_uint(vr1[nt * 8]);
                mma_tf32(o[nt], a0, a1, a2, a3, bb0, bb1);
            }
        }
    }

    // ---- normalize + write AttnOut[token][h*64 + d] ----
    const float inv0 = 1.0f / l0, inv1 = 1.0f / l1;
    float* O0 = O + (size_t)row0 * DMODEL + h * DKH + 2 * tig;
    float* O1 = O + (size_t)row1 * DMODEL + h * DKH + 2 * tig;
#pragma unroll
    for (int nt = 0; nt < 8; nt++) {
        *(float2*)(O0 + nt * 8) = make_float2(o[nt][0] * inv0, o[nt][1] * inv0);
        *(float2*)(O1 + nt * 8) = make_float2(o[nt][2] * inv1, o[nt][3] * inv1);
    }
}

// ============================================================================
extern "C" void kernel_launch(void* const* d_in, const int* in_sizes, int n_in,
                              void* d_out, int out_size)
{
    const float* x       = (const float*)d_in[0];
    const int*   mask    = (const int*)  d_in[1];
    const float* wq_w    = (const float*)d_in[2];
    const float* wq_b    = (const float*)d_in[3];
    const float* wk_w    = (const float*)d_in[4];
    const float* wk_b    = (const float*)d_in[5];
    const float* wv_w    = (const float*)d_in[6];
    const float* wv_b    = (const float*)d_in[7];
    const float* dense_w = (const float*)d_in[8];
    const float* dense_b = (const float*)d_in[9];
    float* out = (float*)d_out;

    float *Qp, *Kp, *Vp, *AOp;
    unsigned long long* MBp;
    cudaGetSymbolAddress((void**)&Qp,  g_Q);
    cudaGetSymbolAddress((void**)&Kp,  g_K);
    cudaGetSymbolAddress((void**)&Vp,  g_V);
    cudaGetSymbolAddress((void**)&AOp, g_AO);
    cudaGetSymbolAddress((void**)&MBp, g_MB);

    cudaFuncSetAttribute(attn_tc_kernel,
                         cudaFuncAttributeMaxDynamicSharedMemorySize,
                         ATTN_SMEM_BYTES);

    // 0) Bit-pack the mask (S*S int32 -> S x S/64 uint64, 2 MB, L2-resident)
    pack_mask_kernel<<<(S_LEN * 64 * 32) / 256, 256>>>(mask, MBp);

    // 1) Fused QKV projections (tf32 tensor cores, R2 known-good)
    qkv_gemm_kernel<<<dim3(12, S_LEN / 128), 256>>>(
        x, wq_w, wq_b, wk_w, wk_b, wv_w, wv_b, Qp, Kp, Vp);

    // 2) Masked flash attention (512 thr, ldmatrix, cp.async K/V)
    attn_tc_kernel<<<dim3(S_LEN / BQ, NHEAD), 512, ATTN_SMEM_BYTES>>>(
        Qp, Kp, Vp, MBp, AOp);

    // 3) Dense output projection (tf32 tensor cores)
    dense_gemm_kernel<<<dim3(DMODEL / 128, S_LEN / 128), 256>>>(
        AOp, dense_w, dense_b, out);
}